// round 5
// baseline (speedup 1.0000x reference)
#include <cuda_runtime.h>
#include <cstdint>

// Problem constants (fixed by the reference: B=8, N=4096, D=512, K=8192)
#define D_DIM      512
#define NUM_CODES  8192
#define NUM_QUERY  32768      // 8 * 4096

// Tiling
#define TM 64                 // queries per CTA
#define TN 128                // codes per N-iteration
#define KB 8                  // k-slab depth in shared
#define NTHREADS 128          // 16 (tx) x 8 (ty), 8x8 micro-tile each

// Scratch: codebook squared norms (no cudaMalloc allowed)
__device__ float g_cnorm[NUM_CODES];

// ---------------------------------------------------------------------------
// ||c_k||^2 for every code. One block of 128 threads per code (512 floats).
// ---------------------------------------------------------------------------
__global__ void __launch_bounds__(128) cnorm_kernel(const float* __restrict__ cb) {
    const int code = blockIdx.x;
    const float4 v = reinterpret_cast<const float4*>(cb + (size_t)code * D_DIM)[threadIdx.x];
    float s = v.x * v.x + v.y * v.y + v.z * v.z + v.w * v.w;
#pragma unroll
    for (int off = 16; off > 0; off >>= 1)
        s += __shfl_xor_sync(0xffffffffu, s, off);
    __shared__ float ws[4];
    if ((threadIdx.x & 31) == 0) ws[threadIdx.x >> 5] = s;
    __syncthreads();
    if (threadIdx.x == 0) g_cnorm[code] = ws[0] + ws[1] + ws[2] + ws[3];
}

// ---------------------------------------------------------------------------
// Fused SGEMM + argmax( 2*x.c - ||c||^2 )  ==  argmin distance.
// Each CTA owns TM=64 queries, loops over all 8192 codes in TN=128 chunks,
// keeps the running best (value, index) per query in registers.
// Tie-breaking matches jnp.argmin: first (lowest) index wins.
// Output stored as float32 (indices < 8192 are exactly representable).
// ---------------------------------------------------------------------------
__global__ void __launch_bounds__(NTHREADS) vq_argmin_kernel(
    const float* __restrict__ X,     // [32768, 512]
    const float* __restrict__ CB,    // [8192, 512]
    float*       __restrict__ out)   // [32768] float32 code indices
{
    __shared__ float As[KB][TM];     // 8 x 64
    __shared__ float Bs[KB][TN];     // 8 x 128

    const int tid = threadIdx.x;
    const int tx  = tid & 15;        // 0..15 -> code sub-tile
    const int ty  = tid >> 4;        // 0..7  -> query sub-tile
    const int rowBase = blockIdx.x * TM;

    // global-load mapping: each thread loads one float4 of A and two of B per slab
    const int ldRow = tid >> 1;            // 0..63
    const int ldSeg = (tid & 1) << 2;      // 0 or 4

    const float* aPtr  = X  + (size_t)(rowBase + ldRow) * D_DIM + ldSeg;

    float bestV[8];
    int   bestI[8];
#pragma unroll
    for (int i = 0; i < 8; i++) { bestV[i] = -3.402823466e+38f; bestI[i] = 0; }

    for (int nt = 0; nt < NUM_CODES; nt += TN) {
        float acc[8][8];
#pragma unroll
        for (int i = 0; i < 8; i++)
#pragma unroll
            for (int j = 0; j < 8; j++) acc[i][j] = 0.0f;

        const float* bPtr0 = CB + (size_t)(nt + ldRow)      * D_DIM + ldSeg;
        const float* bPtr1 = CB + (size_t)(nt + 64 + ldRow) * D_DIM + ldSeg;

        for (int k0 = 0; k0 < D_DIM; k0 += KB) {
            // stage loads into registers (prev iteration may still be reading smem)
            const float4 av  = *reinterpret_cast<const float4*>(aPtr  + k0);
            const float4 bv0 = *reinterpret_cast<const float4*>(bPtr0 + k0);
            const float4 bv1 = *reinterpret_cast<const float4*>(bPtr1 + k0);

            __syncthreads();   // everyone done reading previous slab
            As[ldSeg + 0][ldRow] = av.x;
            As[ldSeg + 1][ldRow] = av.y;
            As[ldSeg + 2][ldRow] = av.z;
            As[ldSeg + 3][ldRow] = av.w;
            Bs[ldSeg + 0][ldRow] = bv0.x;
            Bs[ldSeg + 1][ldRow] = bv0.y;
            Bs[ldSeg + 2][ldRow] = bv0.z;
            Bs[ldSeg + 3][ldRow] = bv0.w;
            Bs[ldSeg + 0][64 + ldRow] = bv1.x;
            Bs[ldSeg + 1][64 + ldRow] = bv1.y;
            Bs[ldSeg + 2][64 + ldRow] = bv1.z;
            Bs[ldSeg + 3][64 + ldRow] = bv1.w;
            __syncthreads();   // slab visible

#pragma unroll
            for (int kk = 0; kk < KB; kk++) {
                float a[8], b[8];
                *reinterpret_cast<float4*>(a)     = *reinterpret_cast<const float4*>(&As[kk][ty * 8]);
                *reinterpret_cast<float4*>(a + 4) = *reinterpret_cast<const float4*>(&As[kk][ty * 8 + 4]);
                *reinterpret_cast<float4*>(b)     = *reinterpret_cast<const float4*>(&Bs[kk][tx * 8]);
                *reinterpret_cast<float4*>(b + 4) = *reinterpret_cast<const float4*>(&Bs[kk][tx * 8 + 4]);
#pragma unroll
                for (int i = 0; i < 8; i++)
#pragma unroll
                    for (int j = 0; j < 8; j++)
                        acc[i][j] = fmaf(a[i], b[j], acc[i][j]);
            }
        }

        // ---- epilogue: per-row argmax of (2*dot - cnorm) over this 128-code tile
        const int col0 = nt + tx * 8;
        float cn[8];
        *reinterpret_cast<float4*>(cn)     = *reinterpret_cast<const float4*>(&g_cnorm[col0]);
        *reinterpret_cast<float4*>(cn + 4) = *reinterpret_cast<const float4*>(&g_cnorm[col0 + 4]);

#pragma unroll
        for (int i = 0; i < 8; i++) {
            float v  = fmaf(2.0f, acc[i][0], -cn[0]);
            int  idx = col0;
#pragma unroll
            for (int j = 1; j < 8; j++) {
                float s = fmaf(2.0f, acc[i][j], -cn[j]);
                if (s > v) { v = s; idx = col0 + j; }   // strict: ties keep lower idx
            }
            // reduce across the 16 tx-lanes (xor<=8 stays inside a 16-lane group)
#pragma unroll
            for (int off = 8; off > 0; off >>= 1) {
                float v2 = __shfl_xor_sync(0xffffffffu, v,   off);
                int   i2 = __shfl_xor_sync(0xffffffffu, idx, off);
                if (v2 > v || (v2 == v && i2 < idx)) { v = v2; idx = i2; }
            }
            // running best across tiles; strict > keeps earlier (lower) index
            if (v > bestV[i]) { bestV[i] = v; bestI[i] = idx; }
        }
    }

    if (tx == 0) {
#pragma unroll
        for (int i = 0; i < 8; i++)
            out[rowBase + ty * 8 + i] = (float)bestI[i];   // exact for idx < 2^24
    }
}

// ---------------------------------------------------------------------------
// Entry point. Inputs disambiguated by element count (robust to ordering):
//   x        : 8*4096*512 = 16,777,216 fp32
//   codebook : 8192*512   =  4,194,304 fp32
// Output: 32768 code indices, stored as float32.
// Graph-capturable: two plain kernel launches on the default stream.
// ---------------------------------------------------------------------------
extern "C" void kernel_launch(void* const* d_in, const int* in_sizes, int n_in,
                              void* d_out, int out_size) {
    const float* x;
    const float* cb;
    if (in_sizes[0] >= in_sizes[1]) {
        x  = (const float*)d_in[0];
        cb = (const float*)d_in[1];
    } else {
        x  = (const float*)d_in[1];
        cb = (const float*)d_in[0];
    }
    float* out = (float*)d_out;

    cnorm_kernel<<<NUM_CODES, 128>>>(cb);
    vq_argmin_kernel<<<NUM_QUERY / TM, NTHREADS>>>(x, cb, out);
}

// round 6
// speedup vs baseline: 1.0001x; 1.0001x over previous
#include <cuda_runtime.h>
#include <cstdint>

// Problem constants (fixed by the reference: B=8, N=4096, D=512, K=8192)
#define D_DIM      512
#define NUM_CODES  8192
#define NUM_QUERY  32768      // 8 * 4096

// Tiling
#define TM 64                 // queries per CTA
#define TN 128                // codes per N-iteration
#define KB 8                  // k-slab depth in shared
#define NTHREADS 128          // 16 (tx) x 8 (ty), 8x8 micro-tile each

// Scratch: codebook squared norms (no cudaMalloc allowed)
__device__ float g_cnorm[NUM_CODES];

// ---------------------------------------------------------------------------
// ||c_k||^2 for every code. One block of 128 threads per code (512 floats).
// ---------------------------------------------------------------------------
__global__ void __launch_bounds__(128) cnorm_kernel(const float* __restrict__ cb) {
    const int code = blockIdx.x;
    const float4 v = reinterpret_cast<const float4*>(cb + (size_t)code * D_DIM)[threadIdx.x];
    float s = v.x * v.x + v.y * v.y + v.z * v.z + v.w * v.w;
#pragma unroll
    for (int off = 16; off > 0; off >>= 1)
        s += __shfl_xor_sync(0xffffffffu, s, off);
    __shared__ float ws[4];
    if ((threadIdx.x & 31) == 0) ws[threadIdx.x >> 5] = s;
    __syncthreads();
    if (threadIdx.x == 0) g_cnorm[code] = ws[0] + ws[1] + ws[2] + ws[3];
}

// ---------------------------------------------------------------------------
// Fused SGEMM + argmax( 2*x.c - ||c||^2 )  ==  argmin distance.
// Each CTA owns TM=64 queries, loops over all 8192 codes in TN=128 chunks,
// keeps the running best (value, index) per query in registers.
// Tie-breaking matches jnp.argmin: first (lowest) index wins.
// Output stored as float32 (indices < 8192 are exactly representable).
// ---------------------------------------------------------------------------
__global__ void __launch_bounds__(NTHREADS) vq_argmin_kernel(
    const float* __restrict__ X,     // [32768, 512]
    const float* __restrict__ CB,    // [8192, 512]
    float*       __restrict__ out)   // [32768] float32 code indices
{
    __shared__ float As[KB][TM];     // 8 x 64
    __shared__ float Bs[KB][TN];     // 8 x 128

    const int tid = threadIdx.x;
    const int tx  = tid & 15;        // 0..15 -> code sub-tile
    const int ty  = tid >> 4;        // 0..7  -> query sub-tile
    const int rowBase = blockIdx.x * TM;

    // global-load mapping: each thread loads one float4 of A and two of B per slab
    const int ldRow = tid >> 1;            // 0..63
    const int ldSeg = (tid & 1) << 2;      // 0 or 4

    const float* aPtr  = X  + (size_t)(rowBase + ldRow) * D_DIM + ldSeg;

    float bestV[8];
    int   bestI[8];
#pragma unroll
    for (int i = 0; i < 8; i++) { bestV[i] = -3.402823466e+38f; bestI[i] = 0; }

    for (int nt = 0; nt < NUM_CODES; nt += TN) {
        float acc[8][8];
#pragma unroll
        for (int i = 0; i < 8; i++)
#pragma unroll
            for (int j = 0; j < 8; j++) acc[i][j] = 0.0f;

        const float* bPtr0 = CB + (size_t)(nt + ldRow)      * D_DIM + ldSeg;
        const float* bPtr1 = CB + (size_t)(nt + 64 + ldRow) * D_DIM + ldSeg;

        for (int k0 = 0; k0 < D_DIM; k0 += KB) {
            // stage loads into registers (prev iteration may still be reading smem)
            const float4 av  = *reinterpret_cast<const float4*>(aPtr  + k0);
            const float4 bv0 = *reinterpret_cast<const float4*>(bPtr0 + k0);
            const float4 bv1 = *reinterpret_cast<const float4*>(bPtr1 + k0);

            __syncthreads();   // everyone done reading previous slab
            As[ldSeg + 0][ldRow] = av.x;
            As[ldSeg + 1][ldRow] = av.y;
            As[ldSeg + 2][ldRow] = av.z;
            As[ldSeg + 3][ldRow] = av.w;
            Bs[ldSeg + 0][ldRow] = bv0.x;
            Bs[ldSeg + 1][ldRow] = bv0.y;
            Bs[ldSeg + 2][ldRow] = bv0.z;
            Bs[ldSeg + 3][ldRow] = bv0.w;
            Bs[ldSeg + 0][64 + ldRow] = bv1.x;
            Bs[ldSeg + 1][64 + ldRow] = bv1.y;
            Bs[ldSeg + 2][64 + ldRow] = bv1.z;
            Bs[ldSeg + 3][64 + ldRow] = bv1.w;
            __syncthreads();   // slab visible

#pragma unroll
            for (int kk = 0; kk < KB; kk++) {
                float a[8], b[8];
                *reinterpret_cast<float4*>(a)     = *reinterpret_cast<const float4*>(&As[kk][ty * 8]);
                *reinterpret_cast<float4*>(a + 4) = *reinterpret_cast<const float4*>(&As[kk][ty * 8 + 4]);
                *reinterpret_cast<float4*>(b)     = *reinterpret_cast<const float4*>(&Bs[kk][tx * 8]);
                *reinterpret_cast<float4*>(b + 4) = *reinterpret_cast<const float4*>(&Bs[kk][tx * 8 + 4]);
#pragma unroll
                for (int i = 0; i < 8; i++)
#pragma unroll
                    for (int j = 0; j < 8; j++)
                        acc[i][j] = fmaf(a[i], b[j], acc[i][j]);
            }
        }

        // ---- epilogue: per-row argmax of (2*dot - cnorm) over this 128-code tile
        const int col0 = nt + tx * 8;
        float cn[8];
        *reinterpret_cast<float4*>(cn)     = *reinterpret_cast<const float4*>(&g_cnorm[col0]);
        *reinterpret_cast<float4*>(cn + 4) = *reinterpret_cast<const float4*>(&g_cnorm[col0 + 4]);

#pragma unroll
        for (int i = 0; i < 8; i++) {
            float v  = fmaf(2.0f, acc[i][0], -cn[0]);
            int  idx = col0;
#pragma unroll
            for (int j = 1; j < 8; j++) {
                float s = fmaf(2.0f, acc[i][j], -cn[j]);
                if (s > v) { v = s; idx = col0 + j; }   // strict: ties keep lower idx
            }
            // reduce across the 16 tx-lanes (xor<=8 stays inside a 16-lane group)
#pragma unroll
            for (int off = 8; off > 0; off >>= 1) {
                float v2 = __shfl_xor_sync(0xffffffffu, v,   off);
                int   i2 = __shfl_xor_sync(0xffffffffu, idx, off);
                if (v2 > v || (v2 == v && i2 < idx)) { v = v2; idx = i2; }
            }
            // running best across tiles; strict > keeps earlier (lower) index
            if (v > bestV[i]) { bestV[i] = v; bestI[i] = idx; }
        }
    }

    if (tx == 0) {
#pragma unroll
        for (int i = 0; i < 8; i++)
            out[rowBase + ty * 8 + i] = (float)bestI[i];   // exact for idx < 2^24
    }
}

// ---------------------------------------------------------------------------
// Entry point. Inputs disambiguated by element count (robust to ordering):
//   x        : 8*4096*512 = 16,777,216 fp32
//   codebook : 8192*512   =  4,194,304 fp32
// Output: 32768 code indices, stored as float32.
// Graph-capturable: two plain kernel launches on the default stream.
// ---------------------------------------------------------------------------
extern "C" void kernel_launch(void* const* d_in, const int* in_sizes, int n_in,
                              void* d_out, int out_size) {
    const float* x;
    const float* cb;
    if (in_sizes[0] >= in_sizes[1]) {
        x  = (const float*)d_in[0];
        cb = (const float*)d_in[1];
    } else {
        x  = (const float*)d_in[1];
        cb = (const float*)d_in[0];
    }
    float* out = (float*)d_out;

    cnorm_kernel<<<NUM_CODES, 128>>>(cb);
    vq_argmin_kernel<<<NUM_QUERY / TM, NTHREADS>>>(x, cb, out);
}

// round 7
// speedup vs baseline: 1.0011x; 1.0010x over previous
#include <cuda_runtime.h>
#include <cstdint>

// Problem constants (fixed by the reference: B=8, N=4096, D=512, K=8192)
#define D_DIM      512
#define NUM_CODES  8192
#define NUM_QUERY  32768      // 8 * 4096

// Tiling
#define TM 64                 // queries per CTA
#define TN 128                // codes per N-iteration
#define KB 8                  // k-slab depth in shared
#define NTHREADS 128          // 16 (tx) x 8 (ty), 8x8 micro-tile each

// Scratch: codebook squared norms (no cudaMalloc allowed)
__device__ float g_cnorm[NUM_CODES];

// ---------------------------------------------------------------------------
// ||c_k||^2 for every code. One block of 128 threads per code (512 floats).
// ---------------------------------------------------------------------------
__global__ void __launch_bounds__(128) cnorm_kernel(const float* __restrict__ cb) {
    const int code = blockIdx.x;
    const float4 v = reinterpret_cast<const float4*>(cb + (size_t)code * D_DIM)[threadIdx.x];
    float s = v.x * v.x + v.y * v.y + v.z * v.z + v.w * v.w;
#pragma unroll
    for (int off = 16; off > 0; off >>= 1)
        s += __shfl_xor_sync(0xffffffffu, s, off);
    __shared__ float ws[4];
    if ((threadIdx.x & 31) == 0) ws[threadIdx.x >> 5] = s;
    __syncthreads();
    if (threadIdx.x == 0) g_cnorm[code] = ws[0] + ws[1] + ws[2] + ws[3];
}

// ---------------------------------------------------------------------------
// Fused SGEMM + argmax( 2*x.c - ||c||^2 )  ==  argmin distance.
// Each CTA owns TM=64 queries, loops over all 8192 codes in TN=128 chunks,
// keeps the running best (value, index) per query in registers.
// Tie-breaking matches jnp.argmin: first (lowest) index wins.
// Output stored as float32 (indices < 8192 are exactly representable).
// ---------------------------------------------------------------------------
__global__ void __launch_bounds__(NTHREADS) vq_argmin_kernel(
    const float* __restrict__ X,     // [32768, 512]
    const float* __restrict__ CB,    // [8192, 512]
    float*       __restrict__ out)   // [32768] float32 code indices
{
    __shared__ float As[KB][TM];     // 8 x 64
    __shared__ float Bs[KB][TN];     // 8 x 128

    const int tid = threadIdx.x;
    const int tx  = tid & 15;        // 0..15 -> code sub-tile
    const int ty  = tid >> 4;        // 0..7  -> query sub-tile
    const int rowBase = blockIdx.x * TM;

    // global-load mapping: each thread loads one float4 of A and two of B per slab
    const int ldRow = tid >> 1;            // 0..63
    const int ldSeg = (tid & 1) << 2;      // 0 or 4

    const float* aPtr  = X  + (size_t)(rowBase + ldRow) * D_DIM + ldSeg;

    float bestV[8];
    int   bestI[8];
#pragma unroll
    for (int i = 0; i < 8; i++) { bestV[i] = -3.402823466e+38f; bestI[i] = 0; }

    for (int nt = 0; nt < NUM_CODES; nt += TN) {
        float acc[8][8];
#pragma unroll
        for (int i = 0; i < 8; i++)
#pragma unroll
            for (int j = 0; j < 8; j++) acc[i][j] = 0.0f;

        const float* bPtr0 = CB + (size_t)(nt + ldRow)      * D_DIM + ldSeg;
        const float* bPtr1 = CB + (size_t)(nt + 64 + ldRow) * D_DIM + ldSeg;

        for (int k0 = 0; k0 < D_DIM; k0 += KB) {
            // stage loads into registers (prev iteration may still be reading smem)
            const float4 av  = *reinterpret_cast<const float4*>(aPtr  + k0);
            const float4 bv0 = *reinterpret_cast<const float4*>(bPtr0 + k0);
            const float4 bv1 = *reinterpret_cast<const float4*>(bPtr1 + k0);

            __syncthreads();   // everyone done reading previous slab
            As[ldSeg + 0][ldRow] = av.x;
            As[ldSeg + 1][ldRow] = av.y;
            As[ldSeg + 2][ldRow] = av.z;
            As[ldSeg + 3][ldRow] = av.w;
            Bs[ldSeg + 0][ldRow] = bv0.x;
            Bs[ldSeg + 1][ldRow] = bv0.y;
            Bs[ldSeg + 2][ldRow] = bv0.z;
            Bs[ldSeg + 3][ldRow] = bv0.w;
            Bs[ldSeg + 0][64 + ldRow] = bv1.x;
            Bs[ldSeg + 1][64 + ldRow] = bv1.y;
            Bs[ldSeg + 2][64 + ldRow] = bv1.z;
            Bs[ldSeg + 3][64 + ldRow] = bv1.w;
            __syncthreads();   // slab visible

#pragma unroll
            for (int kk = 0; kk < KB; kk++) {
                float a[8], b[8];
                *reinterpret_cast<float4*>(a)     = *reinterpret_cast<const float4*>(&As[kk][ty * 8]);
                *reinterpret_cast<float4*>(a + 4) = *reinterpret_cast<const float4*>(&As[kk][ty * 8 + 4]);
                *reinterpret_cast<float4*>(b)     = *reinterpret_cast<const float4*>(&Bs[kk][tx * 8]);
                *reinterpret_cast<float4*>(b + 4) = *reinterpret_cast<const float4*>(&Bs[kk][tx * 8 + 4]);
#pragma unroll
                for (int i = 0; i < 8; i++)
#pragma unroll
                    for (int j = 0; j < 8; j++)
                        acc[i][j] = fmaf(a[i], b[j], acc[i][j]);
            }
        }

        // ---- epilogue: per-row argmax of (2*dot - cnorm) over this 128-code tile
        const int col0 = nt + tx * 8;
        float cn[8];
        *reinterpret_cast<float4*>(cn)     = *reinterpret_cast<const float4*>(&g_cnorm[col0]);
        *reinterpret_cast<float4*>(cn + 4) = *reinterpret_cast<const float4*>(&g_cnorm[col0 + 4]);

#pragma unroll
        for (int i = 0; i < 8; i++) {
            float v  = fmaf(2.0f, acc[i][0], -cn[0]);
            int  idx = col0;
#pragma unroll
            for (int j = 1; j < 8; j++) {
                float s = fmaf(2.0f, acc[i][j], -cn[j]);
                if (s > v) { v = s; idx = col0 + j; }   // strict: ties keep lower idx
            }
            // reduce across the 16 tx-lanes (xor<=8 stays inside a 16-lane group)
#pragma unroll
            for (int off = 8; off > 0; off >>= 1) {
                float v2 = __shfl_xor_sync(0xffffffffu, v,   off);
                int   i2 = __shfl_xor_sync(0xffffffffu, idx, off);
                if (v2 > v || (v2 == v && i2 < idx)) { v = v2; idx = i2; }
            }
            // running best across tiles; strict > keeps earlier (lower) index
            if (v > bestV[i]) { bestV[i] = v; bestI[i] = idx; }
        }
    }

    if (tx == 0) {
#pragma unroll
        for (int i = 0; i < 8; i++)
            out[rowBase + ty * 8 + i] = (float)bestI[i];   // exact for idx < 2^24
    }
}

// ---------------------------------------------------------------------------
// Entry point. Inputs disambiguated by element count (robust to ordering):
//   x        : 8*4096*512 = 16,777,216 fp32
//   codebook : 8192*512   =  4,194,304 fp32
// Output: 32768 code indices, stored as float32.
// Graph-capturable: two plain kernel launches on the default stream.
// ---------------------------------------------------------------------------
extern "C" void kernel_launch(void* const* d_in, const int* in_sizes, int n_in,
                              void* d_out, int out_size) {
    const float* x;
    const float* cb;
    if (in_sizes[0] >= in_sizes[1]) {
        x  = (const float*)d_in[0];
        cb = (const float*)d_in[1];
    } else {
        x  = (const float*)d_in[1];
        cb = (const float*)d_in[0];
    }
    float* out = (float*)d_out;

    cnorm_kernel<<<NUM_CODES, 128>>>(cb);
    vq_argmin_kernel<<<NUM_QUERY / TM, NTHREADS>>>(x, cb, out);
}

// round 10
// speedup vs baseline: 6.9926x; 6.9851x over previous
#include <cuda_runtime.h>
#include <cuda_bf16.h>
#include <cstdint>

// Problem constants (B=8, N=4096, D=512, K=8192)
#define D_DIM      512
#define NUM_CODES  8192
#define NUM_QUERY  32768

// GEMM tiling: CTA 128x128, 8 warps in 2(M) x 4(N), warp tile 64x32, k-slab 64
#define CTA_M   128
#define CTA_N   128
#define KC      64
#define NTILES  (NUM_CODES / CTA_N)    // 64
#define KSLABS  (D_DIM / KC)           // 8
#define CHUNKS  (NTILES * KSLABS)      // 512
#define THREADS 256
#define NEG_INF (-3.402823466e+38f)

// ---- dynamic smem layout ----
// stage s: A [128x64 bf16, swizzled] @ s*32768, B [128x64] @ s*32768+16384
// cand lists: per (warp_n, row) top-3:  float v[4][128][3], int i[4][128][3]
#define STG_BYTES 32768
#define SM_CANDV  65536
#define SM_CANDI  (65536 + 6144)
#define SMEM_TOTAL (65536 + 12288)     // 77824 B

// ---- device scratch (no cudaMalloc allowed) ----
__device__ __nv_bfloat16 g_xb[(size_t)NUM_QUERY * D_DIM];   // 32MB
__device__ __nv_bfloat16 g_cb[(size_t)NUM_CODES * D_DIM];   //  8MB
__device__ float g_cnorm[NUM_CODES];
__device__ int4  g_cand[NUM_QUERY];

// ============================ PTX helpers (sm_80-level, PTX-portable) ============
__device__ __forceinline__ uint32_t smem_u32(const void* p) {
    uint32_t a;
    asm("{ .reg .u64 t; cvta.to.shared.u64 t, %1; cvt.u32.u64 %0, t; }" : "=r"(a) : "l"(p));
    return a;
}
#define CP_ASYNC16(dst, src) \
    asm volatile("cp.async.cg.shared.global [%0], [%1], 16;" :: "r"(dst), "l"(src))
#define CP_COMMIT() asm volatile("cp.async.commit_group;")
#define LDMATRIX_X4(r, addr) \
    asm volatile("ldmatrix.sync.aligned.m8n8.x4.shared.b16 {%0,%1,%2,%3}, [%4];" \
        : "=r"((r)[0]), "=r"((r)[1]), "=r"((r)[2]), "=r"((r)[3]) : "r"(addr))
#define MMA_BF16(d, a, b) \
    asm volatile("mma.sync.aligned.m16n8k16.row.col.f32.bf16.bf16.f32 " \
        "{%0,%1,%2,%3}, {%4,%5,%6,%7}, {%8,%9}, {%0,%1,%2,%3};" \
        : "+f"((d)[0]), "+f"((d)[1]), "+f"((d)[2]), "+f"((d)[3]) \
        : "r"((a)[0]), "r"((a)[1]), "r"((a)[2]), "r"((a)[3]), "r"((b)[0]), "r"((b)[1]))

// lexicographic "better score": higher value; tie -> lower index (jnp.argmin first-hit)
__device__ __forceinline__ bool better(float v, int i, float w, int j) {
    return (v > w) || (v == w && i < j);
}

// ============================ small kernels ============================
__global__ void __launch_bounds__(256) convert_kernel(const float* __restrict__ src,
                                                      __nv_bfloat16* __restrict__ dst, int n4) {
    int i = blockIdx.x * 256 + threadIdx.x;
    if (i >= n4) return;
    float4 v = reinterpret_cast<const float4*>(src)[i];
    __nv_bfloat162* dp = reinterpret_cast<__nv_bfloat162*>(dst) + 2 * i;
    dp[0] = __halves2bfloat162(__float2bfloat16(v.x), __float2bfloat16(v.y));
    dp[1] = __halves2bfloat162(__float2bfloat16(v.z), __float2bfloat16(v.w));
}

__global__ void __launch_bounds__(128) cnorm_kernel(const float* __restrict__ cb) {
    const int code = blockIdx.x;
    const float4 v = reinterpret_cast<const float4*>(cb + (size_t)code * D_DIM)[threadIdx.x];
    float s = v.x * v.x + v.y * v.y + v.z * v.z + v.w * v.w;
#pragma unroll
    for (int off = 16; off > 0; off >>= 1) s += __shfl_xor_sync(0xffffffffu, s, off);
    __shared__ float ws[4];
    if ((threadIdx.x & 31) == 0) ws[threadIdx.x >> 5] = s;
    __syncthreads();
    if (threadIdx.x == 0) g_cnorm[code] = ws[0] + ws[1] + ws[2] + ws[3];
}

// exact fp32 rescore of 4 candidates per query; one warp per query
__global__ void __launch_bounds__(256) rescore_kernel(const float* __restrict__ X,
    const float* __restrict__ CB, const int4* __restrict__ cand, float* __restrict__ out) {
    const int q = blockIdx.x * 8 + (threadIdx.x >> 5);
    const int lane = threadIdx.x & 31;
    const int4 c4 = cand[q];
    int idx[4] = {c4.x, c4.y, c4.z, c4.w};
    float d[4] = {0.f, 0.f, 0.f, 0.f};
    const float4* xr = reinterpret_cast<const float4*>(X + (size_t)q * D_DIM);
#pragma unroll
    for (int p = 0; p < 4; p++) {
        const float4 xv = xr[lane + 32 * p];
#pragma unroll
        for (int k = 0; k < 4; k++) {
            const float4 cv = reinterpret_cast<const float4*>(CB + (size_t)idx[k] * D_DIM)[lane + 32 * p];
            float t;
            t = xv.x - cv.x; d[k] = fmaf(t, t, d[k]);
            t = xv.y - cv.y; d[k] = fmaf(t, t, d[k]);
            t = xv.z - cv.z; d[k] = fmaf(t, t, d[k]);
            t = xv.w - cv.w; d[k] = fmaf(t, t, d[k]);
        }
    }
#pragma unroll
    for (int k = 0; k < 4; k++)
#pragma unroll
        for (int o = 16; o > 0; o >>= 1) d[k] += __shfl_xor_sync(0xffffffffu, d[k], o);
    if (lane == 0) {
        float bd = d[0]; int bi = idx[0];
#pragma unroll
        for (int k = 1; k < 4; k++)
            if (d[k] < bd || (d[k] == bd && idx[k] < bi)) { bd = d[k]; bi = idx[k]; }
        out[q] = (float)bi;
    }
}

// ============================ main fused GEMM+argtop kernel ============================
__device__ __forceinline__ void insert3(float* V, int* I, float v, int ix) {
    if (better(v, ix, V[0], I[0])) { V[2]=V[1]; I[2]=I[1]; V[1]=V[0]; I[1]=I[0]; V[0]=v; I[0]=ix; }
    else if (better(v, ix, V[1], I[1])) { V[2]=V[1]; I[2]=I[1]; V[1]=v; I[1]=ix; }
    else if (better(v, ix, V[2], I[2])) { V[2]=v; I[2]=ix; }
}

__global__ void __launch_bounds__(THREADS, 2) vq_main(
    const __nv_bfloat16* __restrict__ Xb,
    const __nv_bfloat16* __restrict__ Cb,
    const float* __restrict__ cnorm,
    int4* __restrict__ cand)
{
    extern __shared__ char smem[];
    const uint32_t sbase = smem_u32(smem);
    const int tid = threadIdx.x, lane = tid & 31, wid = tid >> 5;
    const int warp_m = wid >> 2, warp_n = wid & 3;      // 2 x 4 warp grid
    const int rowBase = blockIdx.x * CTA_M;

    float* cv = reinterpret_cast<float*>(smem + SM_CANDV);
    int*   ci = reinterpret_cast<int*>(smem + SM_CANDI);
    for (int i = tid; i < 4 * 128 * 3; i += THREADS) { cv[i] = NEG_INF; ci[i] = 0; }
    __syncthreads();

    float acc[4][4][4];
#pragma unroll
    for (int m = 0; m < 4; m++)
#pragma unroll
        for (int n = 0; n < 4; n++)
#pragma unroll
            for (int e = 0; e < 4; e++) acc[m][n][e] = 0.f;

    // ---- async slab loader (A: queries, B: codes; XOR-swizzled 16B granules) ----
    auto issue = [&](int cnt, int stage) {
        const int ntile = cnt >> 3, k0 = (cnt & 7) * KC;
        const uint32_t sA = sbase + stage * STG_BYTES;
        const uint32_t sB = sA + 16384;
#pragma unroll
        for (int g = tid; g < 1024; g += THREADS) {
            const int r = g >> 3, c = g & 7;
            const uint32_t sw = (uint32_t)(r * 128 + ((c ^ (r & 7)) << 4));
            CP_ASYNC16(sA + sw, Xb + (size_t)(rowBase + r) * D_DIM + k0 + c * 8);
            CP_ASYNC16(sB + sw, Cb + (size_t)(ntile * CTA_N + r) * D_DIM + k0 + c * 8);
        }
    };

    issue(0, 0);
    CP_COMMIT();

    for (int cnt = 0; cnt < CHUNKS; cnt++) {
        const int s = cnt & 1;
        if (cnt + 1 < CHUNKS) {
            issue(cnt + 1, s ^ 1);
            CP_COMMIT();
            asm volatile("cp.async.wait_group 1;");
        } else {
            asm volatile("cp.async.wait_group 0;");
        }
        __syncthreads();

        // ---- compute one k64 slab: 4 k16 steps ----
        const uint32_t sA = sbase + s * STG_BYTES;
        const uint32_t sB = sA + 16384;
#pragma unroll
        for (int kk = 0; kk < 4; kk++) {
            uint32_t a[4][4], b[4][2];
#pragma unroll
            for (int mt = 0; mt < 4; mt++) {
                const int row = warp_m * 64 + mt * 16 + (lane & 15);
                const int g = 2 * kk + (lane >> 4);
                LDMATRIX_X4(a[mt], sA + row * 128 + (((g ^ (row & 7))) << 4));
            }
#pragma unroll
            for (int h = 0; h < 2; h++) {
                const int nrow = warp_n * 32 + h * 16 + ((lane >> 4) << 3) + (lane & 7);
                const int g = 2 * kk + ((lane >> 3) & 1);
                uint32_t r4[4];
                LDMATRIX_X4(r4, sB + nrow * 128 + (((g ^ (nrow & 7))) << 4));
                b[2 * h][0] = r4[0]; b[2 * h][1] = r4[1];
                b[2 * h + 1][0] = r4[2]; b[2 * h + 1][1] = r4[3];
            }
#pragma unroll
            for (int mt = 0; mt < 4; mt++)
#pragma unroll
                for (int nt = 0; nt < 4; nt++)
                    MMA_BF16(acc[mt][nt], a[mt], b[nt]);
        }

        // ---- per-N-tile fused epilogue ----
        if ((cnt & 7) == 7) {
            const int ntile = cnt >> 3;
            const int colq = ntile * CTA_N + warp_n * 32 + (lane & 3) * 2;
            float cn0[4], cn1[4];
#pragma unroll
            for (int nt = 0; nt < 4; nt++) { cn0[nt] = cnorm[colq + nt * 8]; cn1[nt] = cnorm[colq + nt * 8 + 1]; }

#pragma unroll
            for (int mt = 0; mt < 4; mt++) {
#pragma unroll
                for (int half = 0; half < 2; half++) {
                    const int row = warp_m * 64 + mt * 16 + (lane >> 2) + half * 8;
                    float v1 = NEG_INF, v2 = NEG_INF; int i1 = 0, i2 = 0;
#pragma unroll
                    for (int nt = 0; nt < 4; nt++) {
                        const int c0 = colq + nt * 8;
                        const float s0 = fmaf(2.f, acc[mt][nt][half * 2],     -cn0[nt]);
                        const float s1 = fmaf(2.f, acc[mt][nt][half * 2 + 1], -cn1[nt]);
                        if (better(s0, c0, v1, i1))      { v2 = v1; i2 = i1; v1 = s0; i1 = c0; }
                        else if (better(s0, c0, v2, i2)) { v2 = s0; i2 = c0; }
                        if (better(s1, c0 + 1, v1, i1))      { v2 = v1; i2 = i1; v1 = s1; i1 = c0 + 1; }
                        else if (better(s1, c0 + 1, v2, i2)) { v2 = s1; i2 = c0 + 1; }
                    }
                    // merge top-2 across the 4 lanes of the quad (xor 1, 2)
#pragma unroll
                    for (int off = 1; off <= 2; off <<= 1) {
                        const float u1 = __shfl_xor_sync(0xffffffffu, v1, off);
                        const int   j1 = __shfl_xor_sync(0xffffffffu, i1, off);
                        const float u2 = __shfl_xor_sync(0xffffffffu, v2, off);
                        const int   j2 = __shfl_xor_sync(0xffffffffu, i2, off);
                        if (better(u1, j1, v1, i1))      { v2 = v1; i2 = i1; v1 = u1; i1 = j1; }
                        else if (better(u1, j1, v2, i2)) { v2 = u1; i2 = j1; }
                        if (better(u2, j2, v2, i2)) {
                            if (better(u2, j2, v1, i1)) { v2 = v1; i2 = i1; v1 = u2; i1 = j2; }
                            else                         { v2 = u2; i2 = j2; }
                        }
                    }
                    if ((lane & 3) == 0) {   // quad leader updates (warp_n,row) top-3 list
                        const int base = (warp_n * 128 + row) * 3;
                        insert3(cv + base, ci + base, v1, i1);
                        insert3(cv + base, ci + base, v2, i2);
                    }
                }
            }
#pragma unroll
            for (int m = 0; m < 4; m++)
#pragma unroll
                for (int n = 0; n < 4; n++)
#pragma unroll
                    for (int e = 0; e < 4; e++) acc[m][n][e] = 0.f;
        }
        __syncthreads();
    }

    // ---- merge 4 quarters x top-3 -> global top-4 candidates per query ----
    if (tid < CTA_M) {
        float bv[4] = {NEG_INF, NEG_INF, NEG_INF, NEG_INF};
        int   bi[4] = {0, 0, 0, 0};
#pragma unroll
        for (int w = 0; w < 4; w++)
#pragma unroll
            for (int e = 0; e < 3; e++) {
                const float v = cv[(w * 128 + tid) * 3 + e];
                const int  ix = ci[(w * 128 + tid) * 3 + e];
                if (better(v, ix, bv[0], bi[0])) {
                    bv[3]=bv[2]; bi[3]=bi[2]; bv[2]=bv[1]; bi[2]=bi[1];
                    bv[1]=bv[0]; bi[1]=bi[0]; bv[0]=v; bi[0]=ix;
                } else if (better(v, ix, bv[1], bi[1])) {
                    bv[3]=bv[2]; bi[3]=bi[2]; bv[2]=bv[1]; bi[2]=bi[1]; bv[1]=v; bi[1]=ix;
                } else if (better(v, ix, bv[2], bi[2])) {
                    bv[3]=bv[2]; bi[3]=bi[2]; bv[2]=v; bi[2]=ix;
                } else if (better(v, ix, bv[3], bi[3])) {
                    bv[3]=v; bi[3]=ix;
                }
            }
        cand[rowBase + tid] = make_int4(bi[0], bi[1], bi[2], bi[3]);
    }
}

// ============================ entry point ============================
extern "C" void kernel_launch(void* const* d_in, const int* in_sizes, int n_in,
                              void* d_out, int out_size) {
    const float *x, *cb;
    if (in_sizes[0] >= in_sizes[1]) { x = (const float*)d_in[0]; cb = (const float*)d_in[1]; }
    else                            { x = (const float*)d_in[1]; cb = (const float*)d_in[0]; }
    float* out = (float*)d_out;

    void *pxb, *pcb, *pcn, *pcd;
    cudaGetSymbolAddress(&pxb, g_xb);
    cudaGetSymbolAddress(&pcb, g_cb);
    cudaGetSymbolAddress(&pcn, g_cnorm);
    cudaGetSymbolAddress(&pcd, g_cand);

    cudaFuncSetAttribute(vq_main, cudaFuncAttributeMaxDynamicSharedMemorySize, SMEM_TOTAL);

    convert_kernel<<<(NUM_QUERY * D_DIM / 4 + 255) / 256, 256>>>(x, (__nv_bfloat16*)pxb, NUM_QUERY * D_DIM / 4);
    convert_kernel<<<(NUM_CODES * D_DIM / 4 + 255) / 256, 256>>>(cb, (__nv_bfloat16*)pcb, NUM_CODES * D_DIM / 4);
    cnorm_kernel<<<NUM_CODES, 128>>>(cb);
    vq_main<<<NUM_QUERY / CTA_M, THREADS, SMEM_TOTAL>>>(
        (const __nv_bfloat16*)pxb, (const __nv_bfloat16*)pcb, (const float*)pcn, (int4*)pcd);
    rescore_kernel<<<NUM_QUERY / 8, 256>>>(x, cb, (const int4*)pcd, out);
}